// round 5
// baseline (speedup 1.0000x reference)
#include <cuda_runtime.h>
#include <cuda_bf16.h>
#include <cstdint>

#define KTAGS 11
#define TT    2048
#define BB    4096
#define CH    8
#define NCHK  (TT / CH)        // 256
#define DEPTH 4
#define SEQ_PB 20              // 10 groups x 2 packed seqs
#define FSTR  92               // floats per seq-chunk slot (368 B, 16B aligned)
#define TSTR  12               // ints per seq-chunk tag slot (48 B)
#define START_TAG 10
#define STOP_TAG  9

typedef unsigned long long u64;

__device__ __forceinline__ u64 pk(float lo, float hi) {
    u64 d;
    asm("mov.b64 %0,{%1,%2};" : "=l"(d) : "r"(__float_as_uint(lo)), "r"(__float_as_uint(hi)));
    return d;
}
__device__ __forceinline__ void upk(u64 v, float& lo, float& hi) {
    uint32_t l, h;
    asm("mov.b64 {%0,%1},%2;" : "=r"(l), "=r"(h) : "l"(v));
    lo = __uint_as_float(l); hi = __uint_as_float(h);
}
__device__ __forceinline__ u64 f2fma(u64 a, u64 b, u64 c) {
    u64 d; asm("fma.rn.f32x2 %0,%1,%2,%3;" : "=l"(d) : "l"(a), "l"(b), "l"(c)); return d;
}
__device__ __forceinline__ u64 f2mul(u64 a, u64 b) {
    u64 d; asm("mul.rn.f32x2 %0,%1,%2;" : "=l"(d) : "l"(a), "l"(b)); return d;
}
__device__ __forceinline__ u64 f2add(u64 a, u64 b) {
    u64 d; asm("add.rn.f32x2 %0,%1,%2;" : "=l"(d) : "l"(a), "l"(b)); return d;
}

// One packed forward step: two sequences (A in lo halves, B in hi halves).
template<bool NORM>
__device__ __forceinline__ void crf_step(
    const float* __restrict__ sfA, const float* __restrict__ sfB, int fo,
    int tgA, int tgB,
    const u64 (&Ep)[3][9], int peer1, int peer2, int row0,
    u64 (&a)[3], double& LA, double& LB,
    float& hA, float& hB, int& tpA, int& tpB,
    const float* __restrict__ s_trans)
{
    float fA0 = sfA[fo], fA1 = sfA[fo + 1], fA2 = sfA[fo + 2];
    float fB0 = sfB[fo], fB1 = sfB[fo + 1], fB2 = sfB[fo + 2];

    u64 b0 = __shfl_sync(0xffffffffu, a[0], peer1);
    u64 b1 = __shfl_sync(0xffffffffu, a[1], peer1);
    u64 b2 = __shfl_sync(0xffffffffu, a[2], peer1);
    u64 c0 = __shfl_sync(0xffffffffu, a[0], peer2);
    u64 c1 = __shfl_sync(0xffffffffu, a[1], peer2);
    u64 c2 = __shfl_sync(0xffffffffu, a[2], peer2);

    u64 s[3];
#pragma unroll
    for (int i = 0; i < 3; i++) {
        u64 t1 = f2mul(Ep[i][0], a[0]);
        t1 = f2fma(Ep[i][1], a[1], t1);
        t1 = f2fma(Ep[i][2], a[2], t1);
        u64 t2 = f2mul(Ep[i][3], b0);
        t2 = f2fma(Ep[i][4], b1, t2);
        t2 = f2fma(Ep[i][5], b2, t2);
        u64 t3 = f2mul(Ep[i][6], c0);
        t3 = f2fma(Ep[i][7], c1, t3);
        t3 = f2fma(Ep[i][8], c2, t3);
        s[i] = f2add(t1, f2add(t2, t3));
    }

    u64 ef0 = pk(__expf(fA0), __expf(fB0));
    u64 ef1 = pk(__expf(fA1), __expf(fB1));
    u64 ef2 = pk(__expf(fA2), __expf(fB2));

    if (NORM) {
        float mA, mB, xA, xB;
        upk(a[0], mA, mB);
        upk(a[1], xA, xB); mA = fmaxf(mA, xA); mB = fmaxf(mB, xB);
        upk(a[2], xA, xB); mA = fmaxf(mA, xA); mB = fmaxf(mB, xB);
        upk(b0,   xA, xB); mA = fmaxf(mA, xA); mB = fmaxf(mB, xB);
        upk(b1,   xA, xB); mA = fmaxf(mA, xA); mB = fmaxf(mB, xB);
        upk(b2,   xA, xB); mA = fmaxf(mA, xA); mB = fmaxf(mB, xB);
        upk(c0,   xA, xB); mA = fmaxf(mA, xA); mB = fmaxf(mB, xB);
        upk(c1,   xA, xB); mA = fmaxf(mA, xA); mB = fmaxf(mB, xB);
        upk(c2,   xA, xB); mA = fmaxf(mA, xA); mB = fmaxf(mB, xB);
        LA += (double)__logf(mA);
        LB += (double)__logf(mB);
        u64 rr = pk(__fdividef(1.0f, mA), __fdividef(1.0f, mB));
        ef0 = f2mul(ef0, rr); ef1 = f2mul(ef1, rr); ef2 = f2mul(ef2, rr);
    }

    a[0] = f2mul(ef0, s[0]);
    a[1] = f2mul(ef1, s[1]);
    a[2] = f2mul(ef2, s[2]);

    // gold score (owner lane of the row accumulates emission + transition)
    unsigned dA = (unsigned)(tgA - row0);
    if (dA < 3u) {
        float fs = (dA == 0) ? fA0 : ((dA == 1) ? fA1 : fA2);
        hA += fs + s_trans[tgA * KTAGS + tpA];
    }
    tpA = tgA;
    unsigned dB = (unsigned)(tgB - row0);
    if (dB < 3u) {
        float fs = (dB == 0) ? fB0 : ((dB == 1) ? fB1 : fB2);
        hB += fs + s_trans[tgB * KTAGS + tpB];
    }
    tpB = tgB;
}

__global__ void __launch_bounds__(32, 1)
crf_nll_kernel(const float* __restrict__ feats,
               const int*   __restrict__ tags,
               const float* __restrict__ trans,
               float* __restrict__ out)
{
    __shared__ __align__(16) float s_feats[DEPTH][SEQ_PB][FSTR];  // 29440 B
    __shared__ __align__(16) int   s_tags [DEPTH][SEQ_PB][TSTR];  //  3840 B
    __shared__ float s_trans[KTAGS * KTAGS];

    const int lane = threadIdx.x & 31;
    for (int i = lane; i < KTAGS * KTAGS; i += 32) s_trans[i] = trans[i];
    __syncwarp();

    // lane -> (group, k); lanes 30,31 shadow group 0 k=0,1 (results discarded)
    int grp, k;
    if (lane < 30) { grp = lane / 3; k = lane - 3 * grp; }
    else           { grp = 0;        k = lane - 30;      }
    const int glane = 3 * grp;
    const int k1 = (k + 1) % 3, k2 = (k + 2) % 3;
    const int peer1 = glane + k1, peer2 = glane + k2;
    const int row0 = 3 * k;
    const int bA = blockIdx.x * SEQ_PB + grp;        // <= 4089, always valid
    const int bB = bA + 10;                          // may exceed 4095 in last block

    // Packed E (same coefficient in both halves); columns in gather order:
    // q 0..2 own tags 3k.., 3..5 peer1 tags 3k1.., 6..8 peer2 tags 3k2..
    u64 Ep[3][9];
    float SV[3], ES[3];
#pragma unroll
    for (int i = 0; i < 3; i++) {
        const float* tr = &s_trans[(row0 + i) * KTAGS];
#pragma unroll
        for (int q = 0; q < 3; q++) {
            float e0 = __expf(tr[3 * k  + q]);
            float e1 = __expf(tr[3 * k1 + q]);
            float e2 = __expf(tr[3 * k2 + q]);
            Ep[i][q]     = pk(e0, e0);
            Ep[i][3 + q] = pk(e1, e1);
            Ep[i][6 + q] = pk(e2, e2);
        }
        SV[i] = tr[START_TAG];
        ES[i] = __expf(s_trans[STOP_TAG * KTAGS + (row0 + i)]);
    }

    // ---- cp.async plan: 480 16B units per chunk = 32 lanes x 15 units ----
    const char* srcp[15];
    uint32_t    dstp[15];
    bool        isf [15];
#pragma unroll
    for (int r = 0; r < 15; r++) {
        int u  = lane + 32 * r;
        int s  = u / 24;
        int kk = u - 24 * s;
        int bs = blockIdx.x * SEQ_PB + s;
        if (bs >= BB) bs = BB - 1;
        if (kk < 22) {
            isf[r]  = true;
            srcp[r] = (const char*)feats + (size_t)bs * TT * KTAGS * 4 + kk * 16;
            dstp[r] = (uint32_t)__cvta_generic_to_shared(&s_feats[0][s][kk * 4]);
        } else {
            isf[r]  = false;
            srcp[r] = (const char*)tags + (size_t)bs * TT * 4 + (kk - 22) * 16;
            dstp[r] = (uint32_t)__cvta_generic_to_shared(&s_tags[0][s][(kk - 22) * 4]);
        }
    }

    auto issue_chunk = [&](int c) {
        int d = c & (DEPTH - 1);
#pragma unroll
        for (int r = 0; r < 15; r++) {
            uint32_t dd = dstp[r] + d * (isf[r] ? (int)sizeof(s_feats[0]) : (int)sizeof(s_tags[0]));
            const char* ss = srcp[r] + (size_t)c * (isf[r] ? CH * KTAGS * 4 : CH * 4);
            asm volatile("cp.async.ca.shared.global [%0], [%1], 16;" :: "r"(dd), "l"(ss));
        }
        asm volatile("cp.async.commit_group;" ::: "memory");
    };

#pragma unroll
    for (int c = 0; c < DEPTH; c++) issue_chunk(c);

    u64   a[3] = {0, 0, 0};
    double LA = 0.0, LB = 0.0, gAd = 0.0, gBd = 0.0;
    int   tpA = START_TAG, tpB = START_TAG;

    for (int c = 0; c < NCHK; c++) {
        asm volatile("cp.async.wait_group %0;" :: "n"(DEPTH - 1) : "memory");
        __syncwarp();

        const int d = c & (DEPTH - 1);
        const float* sfA = &s_feats[d][grp][0];
        const float* sfB = &s_feats[d][10 + grp][0];
        const int*   stA = &s_tags [d][grp][0];
        const int*   stB = &s_tags [d][10 + grp][0];

        float hA = 0.0f, hB = 0.0f;

        if (c == 0) {
            // t = 0: only prev = START survives (other prevs carry exp(-10000) == 0)
            float fA0 = sfA[row0], fA1 = sfA[row0 + 1], fA2 = sfA[row0 + 2];
            float fB0 = sfB[row0], fB1 = sfB[row0 + 1], fB2 = sfB[row0 + 2];
            a[0] = pk(__expf(SV[0] + fA0), __expf(SV[0] + fB0));
            a[1] = pk(__expf(SV[1] + fA1), __expf(SV[1] + fB1));
            a[2] = pk(__expf(SV[2] + fA2), __expf(SV[2] + fB2));
            int tgA = stA[0], tgB = stB[0];
            unsigned dA = (unsigned)(tgA - row0);
            if (dA < 3u) {
                float fs = (dA == 0) ? fA0 : ((dA == 1) ? fA1 : fA2);
                hA += fs + s_trans[tgA * KTAGS + START_TAG];
            }
            tpA = tgA;
            unsigned dB = (unsigned)(tgB - row0);
            if (dB < 3u) {
                float fs = (dB == 0) ? fB0 : ((dB == 1) ? fB1 : fB2);
                hB += fs + s_trans[tgB * KTAGS + START_TAG];
            }
            tpB = tgB;
#pragma unroll
            for (int tc = 1; tc < CH; tc++)
                crf_step<false>(sfA, sfB, tc * KTAGS + row0, stA[tc], stB[tc],
                                Ep, peer1, peer2, row0, a, LA, LB, hA, hB, tpA, tpB, s_trans);
        } else {
            crf_step<true>(sfA, sfB, row0, stA[0], stB[0],
                           Ep, peer1, peer2, row0, a, LA, LB, hA, hB, tpA, tpB, s_trans);
#pragma unroll
            for (int tc = 1; tc < CH; tc++)
                crf_step<false>(sfA, sfB, tc * KTAGS + row0, stA[tc], stB[tc],
                                Ep, peer1, peer2, row0, a, LA, LB, hA, hB, tpA, tpB, s_trans);
        }

        gAd += (double)hA;   // chunk subtotal -> double accumulator (rounding-walk killer)
        gBd += (double)hB;

        __syncwarp();
        if (c + DEPTH < NCHK) issue_chunk(c + DEPTH);
        else asm volatile("cp.async.commit_group;" ::: "memory");
    }

    // finalize: forward = L + log( sum_p a_p * exp(trans[STOP, p]) )
    u64 term = f2mul(a[0], pk(ES[0], ES[0]));
    term = f2fma(a[1], pk(ES[1], ES[1]), term);
    term = f2fma(a[2], pk(ES[2], ES[2]), term);
    u64 t1 = __shfl_sync(0xffffffffu, term, peer1);
    u64 t2 = __shfl_sync(0xffffffffu, term, peer2);
    term = f2add(term, f2add(t1, t2));
    float sumA, sumB;
    upk(term, sumA, sumB);

    double geA = gAd + __shfl_sync(0xffffffffu, gAd, peer1)
                     + __shfl_sync(0xffffffffu, gAd, peer2);
    double geB = gBd + __shfl_sync(0xffffffffu, gBd, peer1)
                     + __shfl_sync(0xffffffffu, gBd, peer2);

    double resA = LA + (double)__logf(sumA) - geA - (double)s_trans[STOP_TAG * KTAGS + tpA];
    double resB = LB + (double)__logf(sumB) - geB - (double)s_trans[STOP_TAG * KTAGS + tpB];

    if (lane < 30 && k == 0) {
        out[bA] = (float)resA;
        if (bB < BB) out[bB] = (float)resB;
    }
}

extern "C" void kernel_launch(void* const* d_in, const int* in_sizes, int n_in,
                              void* d_out, int out_size)
{
    const float* feats = (const float*)d_in[0];
    const int*   tags  = (const int*)d_in[1];
    const float* trans = (const float*)d_in[2];
    float* out = (float*)d_out;

    dim3 grid((BB + SEQ_PB - 1) / SEQ_PB);   // 205 single-warp blocks
    dim3 block(32);
    crf_nll_kernel<<<grid, block>>>(feats, tags, trans, out);
}

// round 6
// speedup vs baseline: 1.0152x; 1.0152x over previous
#include <cuda_runtime.h>
#include <cuda_bf16.h>
#include <cstdint>

#define KTAGS 11
#define TT    2048
#define BB    4096
#define CH    8
#define NCHK  (TT / CH)        // 256
#define DEPTH 4
#define SEQ_PB 20              // 10 groups x 2 packed seqs
#define FSTR  92               // floats per seq-chunk slot (368 B; 352 data + 16 pad)
#define START_TAG 10
#define STOP_TAG  9

typedef unsigned long long u64;

__device__ __forceinline__ u64 pk(float lo, float hi) {
    u64 d;
    asm("mov.b64 %0,{%1,%2};" : "=l"(d) : "r"(__float_as_uint(lo)), "r"(__float_as_uint(hi)));
    return d;
}
__device__ __forceinline__ void upk(u64 v, float& lo, float& hi) {
    uint32_t l, h;
    asm("mov.b64 {%0,%1},%2;" : "=r"(l), "=r"(h) : "l"(v));
    lo = __uint_as_float(l); hi = __uint_as_float(h);
}
__device__ __forceinline__ u64 f2fma(u64 a, u64 b, u64 c) {
    u64 d; asm("fma.rn.f32x2 %0,%1,%2,%3;" : "=l"(d) : "l"(a), "l"(b), "l"(c)); return d;
}
__device__ __forceinline__ u64 f2mul(u64 a, u64 b) {
    u64 d; asm("mul.rn.f32x2 %0,%1,%2;" : "=l"(d) : "l"(a), "l"(b)); return d;
}
__device__ __forceinline__ u64 f2add(u64 a, u64 b) {
    u64 d; asm("add.rn.f32x2 %0,%1,%2;" : "=l"(d) : "l"(a), "l"(b)); return d;
}

// One packed forward step: two sequences (A in lo halves, B in hi halves).
template<bool NORM>
__device__ __forceinline__ void crf_step(
    const float* __restrict__ sfA, const float* __restrict__ sfB, int fo,
    int tgA, int tgB,
    const u64 (&Ep)[3][9], int peer1, int peer2, int row0,
    u64 (&a)[3], double& LA, double& LB,
    float& hA, float& hB, int& tpA, int& tpB,
    const float* __restrict__ s_trans)
{
    float fA0 = sfA[fo], fA1 = sfA[fo + 1], fA2 = sfA[fo + 2];
    float fB0 = sfB[fo], fB1 = sfB[fo + 1], fB2 = sfB[fo + 2];

    u64 b0 = __shfl_sync(0xffffffffu, a[0], peer1);
    u64 b1 = __shfl_sync(0xffffffffu, a[1], peer1);
    u64 b2 = __shfl_sync(0xffffffffu, a[2], peer1);
    u64 c0 = __shfl_sync(0xffffffffu, a[0], peer2);
    u64 c1 = __shfl_sync(0xffffffffu, a[1], peer2);
    u64 c2 = __shfl_sync(0xffffffffu, a[2], peer2);

    u64 s[3];
#pragma unroll
    for (int i = 0; i < 3; i++) {
        u64 t1 = f2mul(Ep[i][0], a[0]);
        t1 = f2fma(Ep[i][1], a[1], t1);
        t1 = f2fma(Ep[i][2], a[2], t1);
        u64 t2 = f2mul(Ep[i][3], b0);
        t2 = f2fma(Ep[i][4], b1, t2);
        t2 = f2fma(Ep[i][5], b2, t2);
        u64 t3 = f2mul(Ep[i][6], c0);
        t3 = f2fma(Ep[i][7], c1, t3);
        t3 = f2fma(Ep[i][8], c2, t3);
        s[i] = f2add(t1, f2add(t2, t3));
    }

    u64 ef0 = pk(__expf(fA0), __expf(fB0));
    u64 ef1 = pk(__expf(fA1), __expf(fB1));
    u64 ef2 = pk(__expf(fA2), __expf(fB2));

    if (NORM) {
        float mA, mB, xA, xB;
        upk(a[0], mA, mB);
        upk(a[1], xA, xB); mA = fmaxf(mA, xA); mB = fmaxf(mB, xB);
        upk(a[2], xA, xB); mA = fmaxf(mA, xA); mB = fmaxf(mB, xB);
        upk(b0,   xA, xB); mA = fmaxf(mA, xA); mB = fmaxf(mB, xB);
        upk(b1,   xA, xB); mA = fmaxf(mA, xA); mB = fmaxf(mB, xB);
        upk(b2,   xA, xB); mA = fmaxf(mA, xA); mB = fmaxf(mB, xB);
        upk(c0,   xA, xB); mA = fmaxf(mA, xA); mB = fmaxf(mB, xB);
        upk(c1,   xA, xB); mA = fmaxf(mA, xA); mB = fmaxf(mB, xB);
        upk(c2,   xA, xB); mA = fmaxf(mA, xA); mB = fmaxf(mB, xB);
        LA += (double)__logf(mA);
        LB += (double)__logf(mB);
        u64 rr = pk(__fdividef(1.0f, mA), __fdividef(1.0f, mB));
        ef0 = f2mul(ef0, rr); ef1 = f2mul(ef1, rr); ef2 = f2mul(ef2, rr);
    }

    a[0] = f2mul(ef0, s[0]);
    a[1] = f2mul(ef1, s[1]);
    a[2] = f2mul(ef2, s[2]);

    // gold score (owner lane of the row accumulates emission + transition)
    unsigned dA = (unsigned)(tgA - row0);
    if (dA < 3u) {
        float fs = (dA == 0) ? fA0 : ((dA == 1) ? fA1 : fA2);
        hA += fs + s_trans[tgA * KTAGS + tpA];
    }
    tpA = tgA;
    unsigned dB = (unsigned)(tgB - row0);
    if (dB < 3u) {
        float fs = (dB == 0) ? fB0 : ((dB == 1) ? fB1 : fB2);
        hB += fs + s_trans[tgB * KTAGS + tpB];
    }
    tpB = tgB;
}

__global__ void __launch_bounds__(32, 1)
crf_nll_kernel(const float* __restrict__ feats,
               const int*   __restrict__ tags,
               const float* __restrict__ trans,
               float* __restrict__ out)
{
    __shared__ __align__(16) float s_feats[DEPTH][SEQ_PB][FSTR];  // 29440 B
    __shared__ __align__(16) int   s_tags [DEPTH][SEQ_PB][CH];    //  2560 B
    __shared__ float s_trans[KTAGS * KTAGS];

    const int lane = threadIdx.x & 31;
    for (int i = lane; i < KTAGS * KTAGS; i += 32) s_trans[i] = trans[i];
    __syncwarp();

    // ---- compact cp.async plan ----
    // lane 0..19 : feats for seq (blk*20 + lane), 22 x 16B units/chunk at +i*16
    // lane 20..29: tags for seqs 2p, 2p+1 (p = lane-20), 4 x 16B units/chunk,
    //              smem offsets also i*16 (two 32B tag slots are contiguous)
    const bool is_feat_lane = (lane < 20);
    const bool is_tag_lane  = (lane >= 20 && lane < 30);
    u64 gbase = 0; uint32_t sbase = 0; uint32_t cstride = 0, sslot = 0;
    uint32_t goff2 = 32, goff3 = 48;  // gmem offsets for units 2,3 (feat default)
    if (is_feat_lane) {
        int bs = blockIdx.x * SEQ_PB + lane; if (bs >= BB) bs = BB - 1;
        gbase   = (u64)(uintptr_t)((const char*)feats + (size_t)bs * TT * KTAGS * 4);
        sbase   = (uint32_t)__cvta_generic_to_shared(&s_feats[0][lane][0]);
        cstride = CH * KTAGS * 4;          // 352 B per chunk
        sslot   = (uint32_t)sizeof(s_feats[0]);
    } else if (is_tag_lane) {
        int p  = lane - 20;
        int bs = blockIdx.x * SEQ_PB + 2 * p;                 // even seq
        if (bs >= BB) bs = BB - 1;
        gbase   = (u64)(uintptr_t)((const char*)tags + (size_t)bs * TT * 4);
        sbase   = (uint32_t)__cvta_generic_to_shared(&s_tags[0][2 * p][0]);
        cstride = CH * 4;                  // 32 B per chunk
        sslot   = (uint32_t)sizeof(s_tags[0]);
        // units 2,3 come from seq bs+1 (clamped): offset TT*4 (+16)
        u64 g2 = gbase + (u64)TT * 4;
        if (bs + 1 >= BB) g2 = gbase;      // clamp duplicate read
        goff2 = (uint32_t)(g2 - gbase);
        goff3 = goff2 + 16;
    }

    auto issue_chunk = [&](int c) {
        const int d = c & (DEPTH - 1);
        u64      g = gbase + (u64)c * cstride;
        uint32_t s = sbase + d * sslot;
        if (lane < 30) {
            asm volatile("cp.async.ca.shared.global [%0], [%1], 16;"      :: "r"(s),      "l"(g));
            asm volatile("cp.async.ca.shared.global [%0+16], [%1+16], 16;" :: "r"(s),     "l"(g));
            asm volatile("cp.async.ca.shared.global [%0+32], [%1], 16;"   :: "r"(s),      "l"(g + goff2));
            asm volatile("cp.async.ca.shared.global [%0+48], [%1], 16;"   :: "r"(s),      "l"(g + goff3));
        }
        if (is_feat_lane) {
#pragma unroll
            for (int i = 4; i < 22; i++) {
                asm volatile("cp.async.ca.shared.global [%0], [%1], 16;"
                             :: "r"(s + i * 16), "l"(g + (u64)(i * 16)));
            }
        }
        asm volatile("cp.async.commit_group;" ::: "memory");
    };

    // lane -> (group, k); lanes 30,31 shadow group 0 k=0,1 (results discarded)
    int grp, k;
    if (lane < 30) { grp = lane / 3; k = lane - 3 * grp; }
    else           { grp = 0;        k = lane - 30;      }
    const int glane = 3 * grp;
    const int k1 = (k + 1) % 3, k2 = (k + 2) % 3;
    const int peer1 = glane + k1, peer2 = glane + k2;
    const int row0 = 3 * k;
    const int bA = blockIdx.x * SEQ_PB + grp;   // <= 4089, always valid
    const int bB = bA + 10;                     // may exceed 4095 in last block

    // Packed E; columns in gather order: q 0..2 own tags 3k.., 3..5 peer1, 6..8 peer2
    u64 Ep[3][9];
    float SV[3], ES[3];
#pragma unroll
    for (int i = 0; i < 3; i++) {
        const float* tr = &s_trans[(row0 + i) * KTAGS];
#pragma unroll
        for (int q = 0; q < 3; q++) {
            float e0 = __expf(tr[3 * k  + q]);
            float e1 = __expf(tr[3 * k1 + q]);
            float e2 = __expf(tr[3 * k2 + q]);
            Ep[i][q]     = pk(e0, e0);
            Ep[i][3 + q] = pk(e1, e1);
            Ep[i][6 + q] = pk(e2, e2);
        }
        SV[i] = tr[START_TAG];
        ES[i] = __expf(s_trans[STOP_TAG * KTAGS + (row0 + i)]);
    }

#pragma unroll
    for (int c = 0; c < DEPTH; c++) issue_chunk(c);

    u64    a[3] = {0, 0, 0};
    double LA = 0.0, LB = 0.0, gAd = 0.0, gBd = 0.0;
    int    tpA = START_TAG, tpB = START_TAG;

    for (int c = 0; c < NCHK; c++) {
        asm volatile("cp.async.wait_group %0;" :: "n"(DEPTH - 1) : "memory");
        __syncwarp();

        const int d = c & (DEPTH - 1);
        const float* sfA = &s_feats[d][grp][0];
        const float* sfB = &s_feats[d][10 + grp][0];
        const int*   stA = &s_tags [d][grp][0];
        const int*   stB = &s_tags [d][10 + grp][0];

        float hA = 0.0f, hB = 0.0f;

        if (c == 0) {
            // t = 0: only prev = START survives (other prevs carry exp(-10000) == 0)
            float fA0 = sfA[row0], fA1 = sfA[row0 + 1], fA2 = sfA[row0 + 2];
            float fB0 = sfB[row0], fB1 = sfB[row0 + 1], fB2 = sfB[row0 + 2];
            a[0] = pk(__expf(SV[0] + fA0), __expf(SV[0] + fB0));
            a[1] = pk(__expf(SV[1] + fA1), __expf(SV[1] + fB1));
            a[2] = pk(__expf(SV[2] + fA2), __expf(SV[2] + fB2));
            int tgA = stA[0], tgB = stB[0];
            unsigned dA = (unsigned)(tgA - row0);
            if (dA < 3u) {
                float fs = (dA == 0) ? fA0 : ((dA == 1) ? fA1 : fA2);
                hA += fs + s_trans[tgA * KTAGS + START_TAG];
            }
            tpA = tgA;
            unsigned dB = (unsigned)(tgB - row0);
            if (dB < 3u) {
                float fs = (dB == 0) ? fB0 : ((dB == 1) ? fB1 : fB2);
                hB += fs + s_trans[tgB * KTAGS + START_TAG];
            }
            tpB = tgB;
#pragma unroll
            for (int tc = 1; tc < CH; tc++)
                crf_step<false>(sfA, sfB, tc * KTAGS + row0, stA[tc], stB[tc],
                                Ep, peer1, peer2, row0, a, LA, LB, hA, hB, tpA, tpB, s_trans);
        } else {
            crf_step<true>(sfA, sfB, row0, stA[0], stB[0],
                           Ep, peer1, peer2, row0, a, LA, LB, hA, hB, tpA, tpB, s_trans);
#pragma unroll
            for (int tc = 1; tc < CH; tc++)
                crf_step<false>(sfA, sfB, tc * KTAGS + row0, stA[tc], stB[tc],
                                Ep, peer1, peer2, row0, a, LA, LB, hA, hB, tpA, tpB, s_trans);
        }

        gAd += (double)hA;
        gBd += (double)hB;

        __syncwarp();
        if (c + DEPTH < NCHK) issue_chunk(c + DEPTH);
        else asm volatile("cp.async.commit_group;" ::: "memory");
    }

    // finalize: forward = L + log( sum_p a_p * exp(trans[STOP, p]) )
    u64 term = f2mul(a[0], pk(ES[0], ES[0]));
    term = f2fma(a[1], pk(ES[1], ES[1]), term);
    term = f2fma(a[2], pk(ES[2], ES[2]), term);
    u64 t1 = __shfl_sync(0xffffffffu, term, peer1);
    u64 t2 = __shfl_sync(0xffffffffu, term, peer2);
    term = f2add(term, f2add(t1, t2));
    float sumA, sumB;
    upk(term, sumA, sumB);

    double geA = gAd + __shfl_sync(0xffffffffu, gAd, peer1)
                     + __shfl_sync(0xffffffffu, gAd, peer2);
    double geB = gBd + __shfl_sync(0xffffffffu, gBd, peer1)
                     + __shfl_sync(0xffffffffu, gBd, peer2);

    double resA = LA + (double)__logf(sumA) - geA - (double)s_trans[STOP_TAG * KTAGS + tpA];
    double resB = LB + (double)__logf(sumB) - geB - (double)s_trans[STOP_TAG * KTAGS + tpB];

    if (lane < 30 && k == 0) {
        out[bA] = (float)resA;
        if (bB < BB) out[bB] = (float)resB;
    }
}

extern "C" void kernel_launch(void* const* d_in, const int* in_sizes, int n_in,
                              void* d_out, int out_size)
{
    const float* feats = (const float*)d_in[0];
    const int*   tags  = (const int*)d_in[1];
    const float* trans = (const float*)d_in[2];
    float* out = (float*)d_out;

    dim3 grid((BB + SEQ_PB - 1) / SEQ_PB);   // 205 single-warp blocks
    dim3 block(32);
    crf_nll_kernel<<<grid, block>>>(feats, tags, trans, out);
}

// round 7
// speedup vs baseline: 1.7122x; 1.6866x over previous
#include <cuda_runtime.h>
#include <cuda_bf16.h>
#include <cstdint>

#define KTAGS 11
#define TT    2048
#define BB    4096
#define CH    8
#define NCHK  (TT / CH)        // 256
#define DEPTH 4
#define WARPS_PB 3
#define SEQ_PW   10
#define SEQ_PB   30
#define THREADS  96
#define FSTR  88               // exactly 352 B per seq-chunk (no pad)
#define START_TAG 10
#define STOP_TAG  9

typedef unsigned long long u64;

// One scalar forward step for one 3-lane group (10 seqs/warp).
template<bool NORM>
__device__ __forceinline__ void crf_step(
    const float* __restrict__ sf, int t, int tg,
    const float (&E)[3][9], int peer1, int peer2, int row0,
    float& a0, float& a1, float& a2,
    float& L, float& h, int& tp,
    const float* __restrict__ s_trans)
{
    const float* fr = &sf[t * KTAGS + row0];
    float f0 = fr[0], f1 = fr[1], f2 = fr[2];

    float b0 = __shfl_sync(0xffffffffu, a0, peer1);
    float b1 = __shfl_sync(0xffffffffu, a1, peer1);
    float b2 = __shfl_sync(0xffffffffu, a2, peer1);
    float c0 = __shfl_sync(0xffffffffu, a0, peer2);
    float c1 = __shfl_sync(0xffffffffu, a1, peer2);
    float c2 = __shfl_sync(0xffffffffu, a2, peer2);

    float s0, s1, s2;
    {
        float t1 = E[0][0] * a0; t1 = fmaf(E[0][1], a1, t1); t1 = fmaf(E[0][2], a2, t1);
        float t2 = E[0][3] * b0; t2 = fmaf(E[0][4], b1, t2); t2 = fmaf(E[0][5], b2, t2);
        float t3 = E[0][6] * c0; t3 = fmaf(E[0][7], c1, t3); t3 = fmaf(E[0][8], c2, t3);
        s0 = t1 + (t2 + t3);
    }
    {
        float t1 = E[1][0] * a0; t1 = fmaf(E[1][1], a1, t1); t1 = fmaf(E[1][2], a2, t1);
        float t2 = E[1][3] * b0; t2 = fmaf(E[1][4], b1, t2); t2 = fmaf(E[1][5], b2, t2);
        float t3 = E[1][6] * c0; t3 = fmaf(E[1][7], c1, t3); t3 = fmaf(E[1][8], c2, t3);
        s1 = t1 + (t2 + t3);
    }
    {
        float t1 = E[2][0] * a0; t1 = fmaf(E[2][1], a1, t1); t1 = fmaf(E[2][2], a2, t1);
        float t2 = E[2][3] * b0; t2 = fmaf(E[2][4], b1, t2); t2 = fmaf(E[2][5], b2, t2);
        float t3 = E[2][6] * c0; t3 = fmaf(E[2][7], c1, t3); t3 = fmaf(E[2][8], c2, t3);
        s2 = t1 + (t2 + t3);
    }

    float ef0 = __expf(f0), ef1 = __expf(f1), ef2 = __expf(f2);
    if (NORM) {
        float m = fmaxf(a0, a1); m = fmaxf(m, a2);
        m = fmaxf(m, b0); m = fmaxf(m, b1); m = fmaxf(m, b2);
        m = fmaxf(m, c0); m = fmaxf(m, c1); m = fmaxf(m, c2);
        L += __logf(m);
        float r = 1.0f / m;
        ef0 *= r; ef1 *= r; ef2 *= r;
    }
    a0 = ef0 * s0;
    a1 = ef1 * s1;
    a2 = ef2 * s2;

    // gold: exactly one lane per group owns tg (tg - row0 in [0,3))
    unsigned dd = (unsigned)(tg - row0);
    if (dd < 3u) {
        float fs = (dd == 0) ? f0 : ((dd == 1) ? f1 : f2);
        h += fs + s_trans[tg * KTAGS + tp];
    }
    tp = tg;
}

__global__ void __launch_bounds__(THREADS, 1)
crf_nll_kernel(const float* __restrict__ feats,
               const int*   __restrict__ tags,
               const float* __restrict__ trans,
               float* __restrict__ out)
{
    __shared__ __align__(16) float s_feats[DEPTH][SEQ_PB][FSTR];  // 42240 B
    __shared__ __align__(16) int   s_tags [DEPTH][SEQ_PB][CH];    //  3840 B
    __shared__ float s_trans[KTAGS * KTAGS];

    const int tid  = threadIdx.x;
    const int w    = tid >> 5;
    const int lane = tid & 31;
    if (tid < KTAGS * KTAGS) s_trans[tid] = trans[tid];
    __syncthreads();

    const int wbase = w * SEQ_PW;     // block-relative first seq of this warp

    // ---- compact staging plan (immediate smem/gmem offsets, minimal regs) ----
    // lane 0..9  : feats of seq (wbase+lane): 22 x 16B units at +i*16
    // lane 10..14: tags of seqs wbase+2p, wbase+2p+1 (p = lane-10): 4 units
    const bool is_feat_lane = (lane < 10);
    const bool is_tag_lane  = (lane >= 10 && lane < 15);
    u64 gbase = 0; uint32_t sbase = 0, cstride = 0, sslot = 0, goff2 = 0;
    if (is_feat_lane) {
        int gs = blockIdx.x * SEQ_PB + wbase + lane; if (gs >= BB) gs = BB - 1;
        gbase   = (u64)(uintptr_t)((const char*)feats + (size_t)gs * TT * KTAGS * 4);
        sbase   = (uint32_t)__cvta_generic_to_shared(&s_feats[0][wbase + lane][0]);
        cstride = CH * KTAGS * 4;           // 352 B
        sslot   = (uint32_t)sizeof(s_feats[0]);
    } else if (is_tag_lane) {
        int p  = lane - 10;
        int gs = blockIdx.x * SEQ_PB + wbase + 2 * p; if (gs >= BB) gs = BB - 1;
        gbase   = (u64)(uintptr_t)((const char*)tags + (size_t)gs * TT * 4);
        sbase   = (uint32_t)__cvta_generic_to_shared(&s_tags[0][wbase + 2 * p][0]);
        cstride = CH * 4;                   // 32 B
        sslot   = (uint32_t)sizeof(s_tags[0]);
        goff2   = (gs + 1 < BB) ? (uint32_t)(TT * 4) : 0u;  // next seq (clamped)
    }

    auto issue_chunk = [&](int c) {
        const int d = c & (DEPTH - 1);
        u64      g = gbase + (u64)c * cstride;
        uint32_t s = sbase + d * sslot;
        if (is_feat_lane) {
#pragma unroll
            for (int i = 0; i < 22; i++)
                asm volatile("cp.async.ca.shared.global [%0], [%1], 16;"
                             :: "r"(s + i * 16), "l"(g + (u64)(i * 16)));
        } else if (is_tag_lane) {
            asm volatile("cp.async.ca.shared.global [%0], [%1], 16;"       :: "r"(s),      "l"(g));
            asm volatile("cp.async.ca.shared.global [%0+16], [%1+16], 16;" :: "r"(s),      "l"(g));
            asm volatile("cp.async.ca.shared.global [%0+32], [%1], 16;"    :: "r"(s),      "l"(g + goff2));
            asm volatile("cp.async.ca.shared.global [%0+48], [%1+16], 16;" :: "r"(s),      "l"(g + goff2));
        }
        asm volatile("cp.async.commit_group;" ::: "memory");
    };

    // lane -> (group, k); lanes 30,31 shadow group 0 k=0,1 (results discarded)
    int grp, k;
    if (lane < 30) { grp = lane / 3; k = lane - 3 * grp; }
    else           { grp = 0;        k = lane - 30;      }
    const int glane = 3 * grp;
    const int k1 = (k + 1) % 3, k2 = (k + 2) % 3;
    const int peer1 = glane + k1, peer2 = glane + k2;
    const int row0 = 3 * k;
    const int gs_c = blockIdx.x * SEQ_PB + wbase + grp;   // global seq of this group

    // E rows (scalar), columns permuted to gather order
    float E[3][9], SV[3], ES[3];
#pragma unroll
    for (int i = 0; i < 3; i++) {
        const float* tr = &s_trans[(row0 + i) * KTAGS];
#pragma unroll
        for (int q = 0; q < 3; q++) {
            E[i][q]     = __expf(tr[3 * k  + q]);
            E[i][3 + q] = __expf(tr[3 * k1 + q]);
            E[i][6 + q] = __expf(tr[3 * k2 + q]);
        }
        SV[i] = tr[START_TAG];
        ES[i] = __expf(s_trans[STOP_TAG * KTAGS + (row0 + i)]);
    }

#pragma unroll
    for (int c = 0; c < DEPTH; c++) issue_chunk(c);

    float a0, a1, a2;
    float L = 0.0f;
    double Ld = 0.0, gd = 0.0;
    int   tp = START_TAG;

    // ---- peel chunk 0 ----
    {
        asm volatile("cp.async.wait_group %0;" :: "n"(DEPTH - 1) : "memory");
        __syncwarp();
        const float* sf = &s_feats[0][wbase + grp][0];
        const int4* tq = (const int4*)&s_tags[0][wbase + grp][0];
        int4 tA = tq[0], tB = tq[1];
        int tgs[8] = {tA.x, tA.y, tA.z, tA.w, tB.x, tB.y, tB.z, tB.w};

        float h = 0.0f;
        // t = 0: only prev = START survives (others carry exp(-10000) == 0)
        float f0 = sf[row0], f1 = sf[row0 + 1], f2 = sf[row0 + 2];
        a0 = __expf(SV[0] + f0);
        a1 = __expf(SV[1] + f1);
        a2 = __expf(SV[2] + f2);
        int tg0 = tgs[0];
        unsigned dd = (unsigned)(tg0 - row0);
        if (dd < 3u) {
            float fs = (dd == 0) ? f0 : ((dd == 1) ? f1 : f2);
            h += fs + s_trans[tg0 * KTAGS + START_TAG];
        }
        tp = tg0;
#pragma unroll
        for (int t = 1; t < CH; t++)
            crf_step<false>(sf, t, tgs[t], E, peer1, peer2, row0, a0, a1, a2, L, h, tp, s_trans);
        gd += (double)h;
        __syncwarp();
        issue_chunk(DEPTH);
    }

    // ---- main loop: single clean body ----
    for (int c = 1; c < NCHK; c++) {
        asm volatile("cp.async.wait_group %0;" :: "n"(DEPTH - 1) : "memory");
        __syncwarp();

        const int d = c & (DEPTH - 1);
        const float* sf = &s_feats[d][wbase + grp][0];
        const int4* tq = (const int4*)&s_tags[d][wbase + grp][0];
        int4 tA = tq[0], tB = tq[1];
        int tgs[8] = {tA.x, tA.y, tA.z, tA.w, tB.x, tB.y, tB.z, tB.w};

        float h = 0.0f;
        crf_step<true >(sf, 0, tgs[0], E, peer1, peer2, row0, a0, a1, a2, L, h, tp, s_trans);
        crf_step<false>(sf, 1, tgs[1], E, peer1, peer2, row0, a0, a1, a2, L, h, tp, s_trans);
        crf_step<false>(sf, 2, tgs[2], E, peer1, peer2, row0, a0, a1, a2, L, h, tp, s_trans);
        crf_step<false>(sf, 3, tgs[3], E, peer1, peer2, row0, a0, a1, a2, L, h, tp, s_trans);
        crf_step<false>(sf, 4, tgs[4], E, peer1, peer2, row0, a0, a1, a2, L, h, tp, s_trans);
        crf_step<false>(sf, 5, tgs[5], E, peer1, peer2, row0, a0, a1, a2, L, h, tp, s_trans);
        crf_step<false>(sf, 6, tgs[6], E, peer1, peer2, row0, a0, a1, a2, L, h, tp, s_trans);
        crf_step<false>(sf, 7, tgs[7], E, peer1, peer2, row0, a0, a1, a2, L, h, tp, s_trans);

        // fold the running log-scale into a double every chunk (precision walk killer)
        Ld += (double)L; L = 0.0f;
        gd += (double)h;

        __syncwarp();
        if (c + DEPTH < NCHK) issue_chunk(c + DEPTH);
        else asm volatile("cp.async.commit_group;" ::: "memory");
    }

    // ---- finalize: forward = Ld + log( sum_p a_p * exp(trans[STOP, p]) ) ----
    float term = a0 * ES[0];
    term = fmaf(a1, ES[1], term);
    term = fmaf(a2, ES[2], term);
    float fsum = term + __shfl_sync(0xffffffffu, term, peer1)
                      + __shfl_sync(0xffffffffu, term, peer2);

    double ge = gd + __shfl_sync(0xffffffffu, gd, peer1)
                   + __shfl_sync(0xffffffffu, gd, peer2);

    double res = Ld + (double)__logf(fsum) - ge - (double)s_trans[STOP_TAG * KTAGS + tp];

    if (lane < 30 && k == 0 && gs_c < BB) out[gs_c] = (float)res;
}

extern "C" void kernel_launch(void* const* d_in, const int* in_sizes, int n_in,
                              void* d_out, int out_size)
{
    const float* feats = (const float*)d_in[0];
    const int*   tags  = (const int*)d_in[1];
    const float* trans = (const float*)d_in[2];
    float* out = (float*)d_out;

    dim3 grid((BB + SEQ_PB - 1) / SEQ_PB);   // 137 blocks, 3 warps each = 411 warps
    dim3 block(THREADS);
    crf_nll_kernel<<<grid, block>>>(feats, tags, trans, out);
}

// round 8
// speedup vs baseline: 1.7793x; 1.0391x over previous
#include <cuda_runtime.h>
#include <cuda_bf16.h>
#include <cstdint>

#define KTAGS 11
#define NST   9
#define TT    2048
#define BB    4096
#define CH    8              // steps per chunk
#define NCHK  (TT / CH)      // 256
#define DEPTH 4
#define WARPS_PB 3
#define SEQ_PW   10          // sequences per warp (3 lanes each, 30 active lanes)
#define SEQ_PB   (WARPS_PB * SEQ_PW)   // 30
#define THREADS  (WARPS_PB * 32)       // 96
#define FSTRIDE  92          // padded floats per seq-chunk slot
#define START_TAG 10
#define STOP_TAG  9

// One forward step for one 3-lane group (10 seqs/warp, scalar fp32).
template<bool NORM>
__device__ __forceinline__ void crf_step(
    const float* __restrict__ sf, int t, int tg,
    const float (&E)[3][9], int peer1, int peer2, int row0,
    float& a0, float& a1, float& a2,
    float& L, float& h, int& tp,
    const float* __restrict__ s_trans)
{
    const float* fr = &sf[t * KTAGS + row0];
    float f0 = fr[0], f1 = fr[1], f2 = fr[2];

    float b0 = __shfl_sync(0xffffffffu, a0, peer1);
    float b1 = __shfl_sync(0xffffffffu, a1, peer1);
    float b2 = __shfl_sync(0xffffffffu, a2, peer1);
    float c0 = __shfl_sync(0xffffffffu, a0, peer2);
    float c1 = __shfl_sync(0xffffffffu, a1, peer2);
    float c2 = __shfl_sync(0xffffffffu, a2, peer2);

    // Single-chain dots (1 MUL + 8 FMA per row); own states first so the head of
    // the chain overlaps the shuffle latency.
    float s0 = E[0][0] * a0;
    s0 = fmaf(E[0][1], a1, s0); s0 = fmaf(E[0][2], a2, s0);
    s0 = fmaf(E[0][3], b0, s0); s0 = fmaf(E[0][4], b1, s0); s0 = fmaf(E[0][5], b2, s0);
    s0 = fmaf(E[0][6], c0, s0); s0 = fmaf(E[0][7], c1, s0); s0 = fmaf(E[0][8], c2, s0);
    float s1 = E[1][0] * a0;
    s1 = fmaf(E[1][1], a1, s1); s1 = fmaf(E[1][2], a2, s1);
    s1 = fmaf(E[1][3], b0, s1); s1 = fmaf(E[1][4], b1, s1); s1 = fmaf(E[1][5], b2, s1);
    s1 = fmaf(E[1][6], c0, s1); s1 = fmaf(E[1][7], c1, s1); s1 = fmaf(E[1][8], c2, s1);
    float s2 = E[2][0] * a0;
    s2 = fmaf(E[2][1], a1, s2); s2 = fmaf(E[2][2], a2, s2);
    s2 = fmaf(E[2][3], b0, s2); s2 = fmaf(E[2][4], b1, s2); s2 = fmaf(E[2][5], b2, s2);
    s2 = fmaf(E[2][6], c0, s2); s2 = fmaf(E[2][7], c1, s2); s2 = fmaf(E[2][8], c2, s2);

    float ef0 = __expf(f0), ef1 = __expf(f1), ef2 = __expf(f2);
    if (NORM) {
        float m = fmaxf(a0, a1); m = fmaxf(m, a2);
        m = fmaxf(m, b0); m = fmaxf(m, b1); m = fmaxf(m, b2);
        m = fmaxf(m, c0); m = fmaxf(m, c1); m = fmaxf(m, c2);
        L += __logf(m);
        float r = 1.0f / m;
        ef0 *= r; ef1 *= r; ef2 *= r;
    }
    a0 = ef0 * s0;
    a1 = ef1 * s1;
    a2 = ef2 * s2;

    // gold: exactly one lane per group owns tg (tg - row0 in [0,3))
    unsigned dd = (unsigned)(tg - row0);
    if (dd < 3u) {
        float fs = (dd == 0) ? f0 : ((dd == 1) ? f1 : f2);
        h += fs + s_trans[tg * KTAGS + tp];
    }
    tp = tg;
}

__global__ void __launch_bounds__(THREADS, 1)
crf_nll_kernel(const float* __restrict__ feats,
               const int*   __restrict__ tags,
               const float* __restrict__ trans,
               float* __restrict__ out)
{
    __shared__ __align__(16) float s_feats[DEPTH][WARPS_PB][SEQ_PW][FSTRIDE]; // 44160 B
    __shared__ __align__(16) int   s_tags [DEPTH][WARPS_PB][SEQ_PW][CH];      //  3840 B
    __shared__ float s_trans[KTAGS * KTAGS];

    const int tid = threadIdx.x;
    if (tid < KTAGS * KTAGS) s_trans[tid] = trans[tid];
    __syncthreads();

    const int w    = tid >> 5;
    const int lane = tid & 31;
    // lane -> (group, k); lanes 30,31 shadow group 0 k=0,1 (results discarded)
    int grp, k;
    if (lane < 30) { grp = lane / 3; k = lane - 3 * grp; }
    else           { grp = 0;        k = lane - 30;      }
    const int glane = 3 * grp;
    const int k1 = (k + 1) % 3, k2 = (k + 2) % 3;
    const int peer1 = glane + k1, peer2 = glane + k2;
    const int row0 = 3 * k;
    const int b = blockIdx.x * SEQ_PB + w * SEQ_PW + grp;
    const bool writer = (lane < 30) && (k == 0) && (b < BB);

    // E[i][q] = exp(trans[row0+i][col(q)]), columns permuted to gather order:
    // q 0..2 own tags 3k.., 3..5 peer1 tags 3k1.., 6..8 peer2 tags 3k2..
    float E[3][9], SV[3], ES[3];
#pragma unroll
    for (int i = 0; i < 3; i++) {
        const float* tr = &s_trans[(row0 + i) * KTAGS];
#pragma unroll
        for (int q = 0; q < 3; q++) {
            E[i][q]     = __expf(tr[3 * k  + q]);
            E[i][3 + q] = __expf(tr[3 * k1 + q]);
            E[i][6 + q] = __expf(tr[3 * k2 + q]);
        }
        SV[i] = tr[START_TAG];
        ES[i] = __expf(s_trans[STOP_TAG * KTAGS + (row0 + i)]);
    }

    // ---- cp.async plan (R2-proven): 240 16B units spread over all 32 lanes ----
    const char* srcp[8];
    uint32_t    dstp[8];
    int         sadv[8];
    int         dadv[8];
    bool        act [8];
#pragma unroll
    for (int r = 0; r < 8; r++) {
        int u = lane + 32 * r;
        act[r] = (u < 240);
        int uu = act[r] ? u : 0;
        int s  = uu / 24;
        int kk = uu % 24;
        int bs = blockIdx.x * SEQ_PB + w * SEQ_PW + s;
        if (bs >= BB) bs = BB - 1;
        if (kk < 22) {
            srcp[r] = (const char*)feats + (size_t)bs * TT * KTAGS * 4 + kk * 16;
            sadv[r] = CH * KTAGS * 4;   // 352 B per chunk
            dstp[r] = (uint32_t)__cvta_generic_to_shared(&s_feats[0][w][s][kk * 4]);
            dadv[r] = (int)sizeof(s_feats[0]);
        } else {
            srcp[r] = (const char*)tags + (size_t)bs * TT * 4 + (kk - 22) * 16;
            sadv[r] = CH * 4;           // 32 B per chunk
            dstp[r] = (uint32_t)__cvta_generic_to_shared(&s_tags[0][w][s][(kk - 22) * 4]);
            dadv[r] = (int)sizeof(s_tags[0]);
        }
    }

    auto issue_chunk = [&](int c) {
        int d = c & (DEPTH - 1);
#pragma unroll
        for (int r = 0; r < 8; r++) {
            if (act[r]) {
                uint32_t dd = dstp[r] + d * dadv[r];
                const char* ss = srcp[r] + (size_t)c * sadv[r];
                asm volatile("cp.async.ca.shared.global [%0], [%1], 16;" :: "r"(dd), "l"(ss));
            }
        }
        asm volatile("cp.async.commit_group;" ::: "memory");
    };

#pragma unroll
    for (int c = 0; c < DEPTH; c++) issue_chunk(c);

    float a0 = 0.f, a1 = 0.f, a2 = 0.f;
    float L = 0.0f;
    double Ld = 0.0, gd = 0.0;
    int   tp = START_TAG;

    for (int c = 0; c < NCHK; c++) {
        asm volatile("cp.async.wait_group %0;" :: "n"(DEPTH - 1) : "memory");
        __syncwarp();

        const int d = c & (DEPTH - 1);
        const float* sf = &s_feats[d][w][grp][0];
        const int*   st = &s_tags [d][w][grp][0];

        float h = 0.0f;
        int tc0 = 0;
        if (c == 0) {
            // t = 0: only prev = START survives (other prevs carry exp(-10000) == 0)
            float f0 = sf[row0], f1 = sf[row0 + 1], f2 = sf[row0 + 2];
            a0 = __expf(SV[0] + f0);
            a1 = __expf(SV[1] + f1);
            a2 = __expf(SV[2] + f2);
            int tg0 = st[0];
            unsigned dd = (unsigned)(tg0 - row0);
            if (dd < 3u) {
                float fs = (dd == 0) ? f0 : ((dd == 1) ? f1 : f2);
                h += fs + s_trans[tg0 * KTAGS + START_TAG];
            }
            tp = tg0;
            tc0 = 1;
        }

#pragma unroll
        for (int tc = 0; tc < CH; tc++) {
            if (tc < tc0) continue;
            if (tc == 0)
                crf_step<true >(sf, tc, st[tc], E, peer1, peer2, row0, a0, a1, a2, L, h, tp, s_trans);
            else
                crf_step<false>(sf, tc, st[tc], E, peer1, peer2, row0, a0, a1, a2, L, h, tp, s_trans);
        }

        // fold chunk subtotals into doubles (off the critical path)
        Ld += (double)L; L = 0.0f;
        gd += (double)h;

        __syncwarp();
        if (c + DEPTH < NCHK) issue_chunk(c + DEPTH);
        else asm volatile("cp.async.commit_group;" ::: "memory");
    }

    // finalize: forward = Ld + log( sum_p a_p * exp(trans[STOP, p]) )
    float term = a0 * ES[0];
    term = fmaf(a1, ES[1], term);
    term = fmaf(a2, ES[2], term);
    float fsum = term + __shfl_sync(0xffffffffu, term, peer1)
                      + __shfl_sync(0xffffffffu, term, peer2);

    double ge = gd + __shfl_sync(0xffffffffu, gd, peer1)
                   + __shfl_sync(0xffffffffu, gd, peer2);

    double res = Ld + (double)__logf(fsum) - ge - (double)s_trans[STOP_TAG * KTAGS + tp];

    if (writer) out[b] = (float)res;
}

extern "C" void kernel_launch(void* const* d_in, const int* in_sizes, int n_in,
                              void* d_out, int out_size)
{
    const float* feats = (const float*)d_in[0];
    const int*   tags  = (const int*)d_in[1];
    const float* trans = (const float*)d_in[2];
    float* out = (float*)d_out;

    dim3 grid((BB + SEQ_PB - 1) / SEQ_PB);   // 137 blocks, single wave
    dim3 block(THREADS);                     // 96 threads = 3 warps = 30 sequences
    crf_nll_kernel<<<grid, block>>>(feats, tags, trans, out);
}

// round 9
// speedup vs baseline: 4.7079x; 2.6460x over previous
#include <cuda_runtime.h>
#include <cuda_bf16.h>
#include <cstdint>

#define KTAGS 11
#define NST   9
#define TT    2048
#define BB    4096
#define CH    8              // steps per chunk
#define NCHK  (TT / CH)      // 256
#define DEPTH 4
#define WARPS_PB 3
#define SEQ_PW   10          // sequences per warp (3 lanes each, 30 active lanes)
#define SEQ_PB   (WARPS_PB * SEQ_PW)   // 30
#define THREADS  (WARPS_PB * 32)       // 96
#define FSTRIDE  92          // padded floats per seq-chunk slot
#define START_TAG 10
#define STOP_TAG  9

// Kahan compensated fold: (s, c) += x.  Adds/subs only — safe under fmad contraction.
__device__ __forceinline__ void kfold(float x, float& s, float& c) {
    float y = x - c;
    float t = s + y;
    c = (t - s) - y;
    s = t;
}

// One forward step in the scaled linear domain (R2-proven structure, fp32 only).
template<bool DONORM>
__device__ __forceinline__ void crf_step(const float* __restrict__ sf, int tc, int tg,
                                         const float* __restrict__ s_trans,
                                         const float (&E)[3][9],
                                         int peer1, int peer2, int row0,
                                         float& a0, float& a1, float& a2,
                                         float& hE, float& hT, float& Lc, int& tagprev)
{
    const float* fr = &sf[tc * KTAGS + row0];
    float f0 = fr[0], f1 = fr[1], f2 = fr[2];

    float b0 = __shfl_sync(0xffffffffu, a0, peer1);
    float b1 = __shfl_sync(0xffffffffu, a1, peer1);
    float b2 = __shfl_sync(0xffffffffu, a2, peer1);
    float c0 = __shfl_sync(0xffffffffu, a0, peer2);
    float c1 = __shfl_sync(0xffffffffu, a1, peer2);
    float c2 = __shfl_sync(0xffffffffu, a2, peer2);

    float s[3];
#pragma unroll
    for (int i = 0; i < 3; i++) {
        float t1 = E[i][0] * a0;
        t1 = fmaf(E[i][1], a1, t1);
        t1 = fmaf(E[i][2], a2, t1);
        float t2 = E[i][3] * b0;
        t2 = fmaf(E[i][4], b1, t2);
        t2 = fmaf(E[i][5], b2, t2);
        float t3 = E[i][6] * c0;
        t3 = fmaf(E[i][7], c1, t3);
        t3 = fmaf(E[i][8], c2, t3);
        s[i] = t1 + (t2 + t3);
    }

    float ef0 = __expf(f0), ef1 = __expf(f1), ef2 = __expf(f2);
    if (DONORM) {
        float m = fmaxf(a0, a1); m = fmaxf(m, a2);
        m = fmaxf(m, b0); m = fmaxf(m, b1); m = fmaxf(m, b2);
        m = fmaxf(m, c0); m = fmaxf(m, c1); m = fmaxf(m, c2);
        Lc += __logf(m);
        float r = 1.0f / m;
        ef0 *= r; ef1 *= r; ef2 *= r;
    }
    a0 = ef0 * s[0];
    a1 = ef1 * s[1];
    a2 = ef2 * s[2];

    // gold score (R2 split: per-lane emission + group-uniform transition)
    unsigned dd = (unsigned)(tg - row0);
    float fsel = f0; if (dd == 1u) fsel = f1; if (dd == 2u) fsel = f2;
    if (dd < 3u) hE += fsel;
    hT += s_trans[tg * KTAGS + tagprev];
    tagprev = tg;
}

__global__ void __launch_bounds__(THREADS, 1)
crf_nll_kernel(const float* __restrict__ feats,
               const int*   __restrict__ tags,
               const float* __restrict__ trans,
               float* __restrict__ out)
{
    __shared__ __align__(16) float s_feats[DEPTH][WARPS_PB][SEQ_PW][FSTRIDE]; // 44160 B
    __shared__ __align__(16) int   s_tags [DEPTH][WARPS_PB][SEQ_PW][CH];      //  3840 B
    __shared__ float s_trans[KTAGS * KTAGS];

    const int tid = threadIdx.x;
    if (tid < KTAGS * KTAGS) s_trans[tid] = trans[tid];
    __syncthreads();

    const int w    = tid >> 5;
    const int lane = tid & 31;
    // lane -> (group, k); lanes 30,31 shadow group 0 k=0,1 (results discarded)
    int grp, k;
    if (lane < 30) { grp = lane / 3; k = lane - 3 * grp; }
    else           { grp = 0;        k = lane - 30;      }
    const int glane = 3 * grp;
    const int k1 = (k + 1) % 3, k2 = (k + 2) % 3;
    const int peer1 = glane + k1, peer2 = glane + k2;
    const int row0 = 3 * k;
    const int b = blockIdx.x * SEQ_PB + w * SEQ_PW + grp;
    const bool writer = (lane < 30) && (k == 0) && (b < BB);

    // E[i][q] = exp(trans[row0+i][col(q)]), columns permuted to gather order
    float E[3][9], SV[3], ES[3];
#pragma unroll
    for (int i = 0; i < 3; i++) {
        const float* tr = &s_trans[(row0 + i) * KTAGS];
#pragma unroll
        for (int q = 0; q < 3; q++) {
            E[i][q]     = __expf(tr[3 * k  + q]);
            E[i][3 + q] = __expf(tr[3 * k1 + q]);
            E[i][6 + q] = __expf(tr[3 * k2 + q]);
        }
        SV[i] = tr[START_TAG];
        ES[i] = __expf(s_trans[STOP_TAG * KTAGS + (row0 + i)]);
    }

    // ---- cp.async plan (R2-proven): 240 16B units spread over all 32 lanes ----
    const char* srcp[8];
    uint32_t    dstp[8];
    int         sadv[8];
    int         dadv[8];
    bool        act [8];
#pragma unroll
    for (int r = 0; r < 8; r++) {
        int u = lane + 32 * r;
        act[r] = (u < 240);
        int uu = act[r] ? u : 0;
        int s  = uu / 24;
        int kk = uu % 24;
        int bs = blockIdx.x * SEQ_PB + w * SEQ_PW + s;
        if (bs >= BB) bs = BB - 1;
        if (kk < 22) {
            srcp[r] = (const char*)feats + (size_t)bs * TT * KTAGS * 4 + kk * 16;
            sadv[r] = CH * KTAGS * 4;   // 352 B per chunk
            dstp[r] = (uint32_t)__cvta_generic_to_shared(&s_feats[0][w][s][kk * 4]);
            dadv[r] = (int)sizeof(s_feats[0]);
        } else {
            srcp[r] = (const char*)tags + (size_t)bs * TT * 4 + (kk - 22) * 16;
            sadv[r] = CH * 4;           // 32 B per chunk
            dstp[r] = (uint32_t)__cvta_generic_to_shared(&s_tags[0][w][s][(kk - 22) * 4]);
            dadv[r] = (int)sizeof(s_tags[0]);
        }
    }

    auto issue_chunk = [&](int c) {
        int d = c & (DEPTH - 1);
#pragma unroll
        for (int r = 0; r < 8; r++) {
            if (act[r]) {
                uint32_t dd = dstp[r] + d * dadv[r];
                const char* ss = srcp[r] + (size_t)c * sadv[r];
                asm volatile("cp.async.ca.shared.global [%0], [%1], 16;" :: "r"(dd), "l"(ss));
            }
        }
        asm volatile("cp.async.commit_group;" ::: "memory");
    };

#pragma unroll
    for (int c = 0; c < DEPTH; c++) issue_chunk(c);

    float a0 = 0.f, a1 = 0.f, a2 = 0.f;
    // Kahan accumulators (fp32 only — no FP64 anywhere)
    float LS = 0.f, LCm = 0.f, gES = 0.f, gEC = 0.f, gTS = 0.f, gTC = 0.f;
    int   tagprev = START_TAG;

    for (int c = 0; c < NCHK; c++) {
        asm volatile("cp.async.wait_group %0;" :: "n"(DEPTH - 1) : "memory");
        __syncwarp();

        const int d = c & (DEPTH - 1);
        const float* sf = &s_feats[d][w][grp][0];
        const int4*  tq = (const int4*)&s_tags[d][w][grp][0];
        int4 tA = tq[0], tB = tq[1];
        int tgs[8] = {tA.x, tA.y, tA.z, tA.w, tB.x, tB.y, tB.z, tB.w};

        float hE = 0.f, hT = 0.f, Lc = 0.f;

        if (c == 0) {
            // t = 0: only prev = START survives (others carry exp(-10000) == 0)
            float f0 = sf[row0], f1 = sf[row0 + 1], f2 = sf[row0 + 2];
            a0 = __expf(SV[0] + f0);
            a1 = __expf(SV[1] + f1);
            a2 = __expf(SV[2] + f2);
            int tg0 = tgs[0];
            unsigned dd = (unsigned)(tg0 - row0);
            float fsel = f0; if (dd == 1u) fsel = f1; if (dd == 2u) fsel = f2;
            if (dd < 3u) hE += fsel;
            hT += s_trans[tg0 * KTAGS + START_TAG];
            tagprev = tg0;
#pragma unroll
            for (int tc = 1; tc < CH; tc++)
                crf_step<false>(sf, tc, tgs[tc], s_trans, E, peer1, peer2, row0,
                                a0, a1, a2, hE, hT, Lc, tagprev);
        } else {
            crf_step<true>(sf, 0, tgs[0], s_trans, E, peer1, peer2, row0,
                           a0, a1, a2, hE, hT, Lc, tagprev);
#pragma unroll
            for (int tc = 1; tc < CH; tc++)
                crf_step<false>(sf, tc, tgs[tc], s_trans, E, peer1, peer2, row0,
                                a0, a1, a2, hE, hT, Lc, tagprev);
        }

        // fold chunk subtotals with Kahan compensation (fp32, off critical path)
        kfold(hE, gES, gEC);
        kfold(hT, gTS, gTC);
        kfold(Lc, LS,  LCm);

        __syncwarp();
        if (c + DEPTH < NCHK) issue_chunk(c + DEPTH);
        else asm volatile("cp.async.commit_group;" ::: "memory");
    }

    // finalize: forward = L + log( sum_p a_p * exp(trans[STOP, p]) )
    float term = a0 * ES[0];
    term = fmaf(a1, ES[1], term);
    term = fmaf(a2, ES[2], term);
    float fsum = term + __shfl_sync(0xffffffffu, term, peer1)
                      + __shfl_sync(0xffffffffu, term, peer2);

    float gE = gES - gEC;  // compensated totals
    float ge = gE + __shfl_sync(0xffffffffu, gE, peer1)
                  + __shfl_sync(0xffffffffu, gE, peer2);
    float gT = gTS - gTC;
    float Lt = LS - LCm;

    float gold_total = ge + gT + s_trans[STOP_TAG * KTAGS + tagprev];
    float res = Lt + __logf(fsum) - gold_total;

    if (writer) out[b] = res;
}

extern "C" void kernel_launch(void* const* d_in, const int* in_sizes, int n_in,
                              void* d_out, int out_size)
{
    const float* feats = (const float*)d_in[0];
    const int*   tags  = (const int*)d_in[1];
    const float* trans = (const float*)d_in[2];
    float* out = (float*)d_out;

    dim3 grid((BB + SEQ_PB - 1) / SEQ_PB);   // 137 blocks, single wave
    dim3 block(THREADS);                     // 96 threads = 3 warps = 30 sequences
    crf_nll_kernel<<<grid, block>>>(feats, tags, trans, out);
}

// round 10
// speedup vs baseline: 5.0327x; 1.0690x over previous
#include <cuda_runtime.h>
#include <cuda_bf16.h>
#include <cstdint>

#define KTAGS 11
#define TT    2048
#define BB    4096
#define CH    8              // steps per chunk
#define NCHK  (TT / CH)      // 256
#define DEPTH 4
#define WARPS_PB 3
#define SEQ_PW   10          // sequences per warp (3 lanes each, 30 active lanes)
#define SEQ_PB   (WARPS_PB * SEQ_PW)   // 30
#define THREADS  (WARPS_PB * 32)       // 96
#define FSTRIDE  92          // padded floats per seq-chunk slot
#define START_TAG 10
#define STOP_TAG  9
#define EX2C 1.4426950408889634f   // log2(e)

__device__ __forceinline__ float ex2f(float x) {
    float r; asm("ex2.approx.f32 %0, %1;" : "=f"(r) : "f"(x)); return r;
}

// Kahan compensated fold (adds/subs only — safe under fmad contraction)
__device__ __forceinline__ void kfold(float x, float& s, float& c) {
    float y = x - c;
    float t = s + y;
    c = (t - s) - y;
    s = t;
}

// One gold-shifted forward step:  a'_j = exp(f_j - f_g - tr_g [- log m]) * sum_p E[j,p] a_p
template<bool DONORM>
__device__ __forceinline__ void crf_step(const float* __restrict__ sf, int tc, int tg,
                                         const float* __restrict__ s_trans,
                                         const float (&E)[3][9],
                                         int peer1, int peer2, int row0,
                                         float& a0, float& a1, float& a2,
                                         float& LS, float& LC, int& tagprev)
{
    const float* fr = &sf[tc * KTAGS + row0];
    float f0 = fr[0], f1 = fr[1], f2 = fr[2];
    float fg  = sf[tc * KTAGS + tg];              // gold feat (group-uniform, smem broadcast)
    float trg = s_trans[tg * KTAGS + tagprev];    // gold transition (group-uniform)

    float b0 = __shfl_sync(0xffffffffu, a0, peer1);
    float b1 = __shfl_sync(0xffffffffu, a1, peer1);
    float b2 = __shfl_sync(0xffffffffu, a2, peer1);
    float c0 = __shfl_sync(0xffffffffu, a0, peer2);
    float c1 = __shfl_sync(0xffffffffu, a1, peer2);
    float c2 = __shfl_sync(0xffffffffu, a2, peer2);

    float s[3];
#pragma unroll
    for (int i = 0; i < 3; i++) {
        float t1 = E[i][0] * a0;
        t1 = fmaf(E[i][1], a1, t1);
        t1 = fmaf(E[i][2], a2, t1);
        float t2 = E[i][3] * b0;
        t2 = fmaf(E[i][4], b1, t2);
        t2 = fmaf(E[i][5], b2, t2);
        float t3 = E[i][6] * c0;
        t3 = fmaf(E[i][7], c1, t3);
        t3 = fmaf(E[i][8], c2, t3);
        s[i] = t1 + (t2 + t3);
    }

    float nd  = -fg - trg;          // gold shift
    float ndc = nd * EX2C;
    if (DONORM) {
        float m = fmaxf(a0, a1); m = fmaxf(m, a2);
        m = fmaxf(m, b0); m = fmaxf(m, b1); m = fmaxf(m, b2);
        m = fmaxf(m, c0); m = fmaxf(m, c1); m = fmaxf(m, c2);
        float lm = __logf(m);
        kfold(lm, LS, LC);
        ndc = fmaf(-lm, EX2C, ndc);   // fold 1/m into the exponent (no rcp, no muls)
    }
    float ef0 = ex2f(fmaf(f0, EX2C, ndc));
    float ef1 = ex2f(fmaf(f1, EX2C, ndc));
    float ef2 = ex2f(fmaf(f2, EX2C, ndc));

    a0 = ef0 * s[0];
    a1 = ef1 * s[1];
    a2 = ef2 * s[2];
    tagprev = tg;
}

__global__ void __launch_bounds__(THREADS, 1)
crf_nll_kernel(const float* __restrict__ feats,
               const int*   __restrict__ tags,
               const float* __restrict__ trans,
               float* __restrict__ out)
{
    __shared__ __align__(16) float s_feats[DEPTH][WARPS_PB][SEQ_PW][FSTRIDE]; // 44160 B
    __shared__ __align__(16) int   s_tags [DEPTH][WARPS_PB][SEQ_PW][CH];      //  3840 B
    __shared__ float s_trans[KTAGS * KTAGS];

    const int tid = threadIdx.x;
    if (tid < KTAGS * KTAGS) s_trans[tid] = trans[tid];
    __syncthreads();

    const int w    = tid >> 5;
    const int lane = tid & 31;
    // lane -> (group, k); lanes 30,31 shadow group 0 k=0,1 (results discarded)
    int grp, k;
    if (lane < 30) { grp = lane / 3; k = lane - 3 * grp; }
    else           { grp = 0;        k = lane - 30;      }
    const int glane = 3 * grp;
    const int k1 = (k + 1) % 3, k2 = (k + 2) % 3;
    const int peer1 = glane + k1, peer2 = glane + k2;
    const int row0 = 3 * k;
    const int b = blockIdx.x * SEQ_PB + w * SEQ_PW + grp;
    const bool writer = (lane < 30) && (k == 0) && (b < BB);

    // E[i][q] = exp(trans[row0+i][col(q)]), columns permuted to gather order
    float E[3][9], SV[3], ES[3];
#pragma unroll
    for (int i = 0; i < 3; i++) {
        const float* tr = &s_trans[(row0 + i) * KTAGS];
#pragma unroll
        for (int q = 0; q < 3; q++) {
            E[i][q]     = __expf(tr[3 * k  + q]);
            E[i][3 + q] = __expf(tr[3 * k1 + q]);
            E[i][6 + q] = __expf(tr[3 * k2 + q]);
        }
        SV[i] = tr[START_TAG];
        ES[i] = __expf(s_trans[STOP_TAG * KTAGS + (row0 + i)]);
    }

    // ---- cp.async plan (R2-proven): 240 16B units spread over all 32 lanes ----
    const char* srcp[8];
    uint32_t    dstp[8];
    int         sadv[8];
    int         dadv[8];
    bool        act [8];
#pragma unroll
    for (int r = 0; r < 8; r++) {
        int u = lane + 32 * r;
        act[r] = (u < 240);
        int uu = act[r] ? u : 0;
        int s  = uu / 24;
        int kk = uu % 24;
        int bs = blockIdx.x * SEQ_PB + w * SEQ_PW + s;
        if (bs >= BB) bs = BB - 1;
        if (kk < 22) {
            srcp[r] = (const char*)feats + (size_t)bs * TT * KTAGS * 4 + kk * 16;
            sadv[r] = CH * KTAGS * 4;   // 352 B per chunk
            dstp[r] = (uint32_t)__cvta_generic_to_shared(&s_feats[0][w][s][kk * 4]);
            dadv[r] = (int)sizeof(s_feats[0]);
        } else {
            srcp[r] = (const char*)tags + (size_t)bs * TT * 4 + (kk - 22) * 16;
            sadv[r] = CH * 4;           // 32 B per chunk
            dstp[r] = (uint32_t)__cvta_generic_to_shared(&s_tags[0][w][s][(kk - 22) * 4]);
            dadv[r] = (int)sizeof(s_tags[0]);
        }
    }

    auto issue_chunk = [&](int c) {
        int d = c & (DEPTH - 1);
#pragma unroll
        for (int r = 0; r < 8; r++) {
            if (act[r]) {
                uint32_t dd = dstp[r] + d * dadv[r];
                const char* ss = srcp[r] + (size_t)c * sadv[r];
                asm volatile("cp.async.ca.shared.global [%0], [%1], 16;" :: "r"(dd), "l"(ss));
            }
        }
        asm volatile("cp.async.commit_group;" ::: "memory");
    };

#pragma unroll
    for (int c = 0; c < DEPTH; c++) issue_chunk(c);

    float a0 = 0.f, a1 = 0.f, a2 = 0.f;
    float LS = 0.f, LC = 0.f;       // Kahan-compensated log-scale (fp32 only)
    int   tagprev = START_TAG;

    for (int c = 0; c < NCHK; c++) {
        asm volatile("cp.async.wait_group %0;" :: "n"(DEPTH - 1) : "memory");
        __syncwarp();

        const int d = c & (DEPTH - 1);
        const float* sf = &s_feats[d][w][grp][0];
        const int4*  tq = (const int4*)&s_tags[d][w][grp][0];
        int4 tA = tq[0], tB = tq[1];
        int tgs[8] = {tA.x, tA.y, tA.z, tA.w, tB.x, tB.y, tB.z, tB.w};

        if (c == 0) {
            // t = 0 (gold-shifted): a_j = exp(SV_j + f_j - f_gold - trans[tg0,START])
            float f0 = sf[row0], f1 = sf[row0 + 1], f2 = sf[row0 + 2];
            int tg0 = tgs[0];
            float fg  = sf[tg0];
            float tr0 = s_trans[tg0 * KTAGS + START_TAG];
            float ndc = (-fg - tr0) * EX2C;
            a0 = ex2f(fmaf(SV[0] + f0, EX2C, ndc));
            a1 = ex2f(fmaf(SV[1] + f1, EX2C, ndc));
            a2 = ex2f(fmaf(SV[2] + f2, EX2C, ndc));
            tagprev = tg0;
#pragma unroll
            for (int tc = 1; tc < CH; tc++)
                crf_step<false>(sf, tc, tgs[tc], s_trans, E, peer1, peer2, row0,
                                a0, a1, a2, LS, LC, tagprev);
        } else {
            crf_step<true>(sf, 0, tgs[0], s_trans, E, peer1, peer2, row0,
                           a0, a1, a2, LS, LC, tagprev);
#pragma unroll
            for (int tc = 1; tc < CH; tc++)
                crf_step<false>(sf, tc, tgs[tc], s_trans, E, peer1, peer2, row0,
                                a0, a1, a2, LS, LC, tagprev);
        }

        __syncwarp();
        if (c + DEPTH < NCHK) issue_chunk(c + DEPTH);
        else asm volatile("cp.async.commit_group;" ::: "memory");
    }

    // finalize: NLL = L + log( sum_p a_p * exp(trans[STOP,p]) ) - trans[STOP, tag_last]
    float term = a0 * ES[0];
    term = fmaf(a1, ES[1], term);
    term = fmaf(a2, ES[2], term);
    float fsum = term + __shfl_sync(0xffffffffu, term, peer1)
                      + __shfl_sync(0xffffffffu, term, peer2);

    float res = (LS - LC) + __logf(fsum) - s_trans[STOP_TAG * KTAGS + tagprev];

    if (writer) out[b] = res;
}

extern "C" void kernel_launch(void* const* d_in, const int* in_sizes, int n_in,
                              void* d_out, int out_size)
{
    const float* feats = (const float*)d_in[0];
    const int*   tags  = (const int*)d_in[1];
    const float* trans = (const float*)d_in[2];
    float* out = (float*)d_out;

    dim3 grid((BB + SEQ_PB - 1) / SEQ_PB);   // 137 blocks, single wave
    dim3 block(THREADS);                     // 96 threads = 3 warps = 30 sequences
    crf_nll_kernel<<<grid, block>>>(feats, tags, trans, out);
}